// round 16
// baseline (speedup 1.0000x reference)
#include <cuda_runtime.h>
#include <math.h>
#include <cstdint>

#define Bn 8
#define Sn 2048
#define En 1024
#define Hn 64
#define NSPLIT 4

// q,k: (h,l) pairs along h, PAIR-PERMUTED [0,4,1,5,2,6,3,7] per 8-pair group.
// v:   [b][h][kvpair] (h,l) pairs along kv, same permutation per group.
__device__ uint32_t g_qi[Bn * Sn * 64];   // q PRE-SCALED by 0.125
__device__ uint32_t g_ki[Bn * Sn * 64];
__device__ uint32_t g_vi[Bn * 64 * 2048];
__device__ float g_op[NSPLIT * Bn * Sn * Hn];
__device__ float g_ml[NSPLIT * Bn * Sn * 2];
__device__ uint32_t g_wi[192 * 1024];     // W: (h,l) pairs along k (natural order)

__device__ __forceinline__ uint32_t smem_u32(const void* p) {
    uint32_t a;
    asm("{ .reg .u64 t; cvta.to.shared.u64 t, %1; cvt.u32.u64 %0, t; }"
        : "=r"(a) : "l"(p));
    return a;
}

#define CP16(dst, src) \
    asm volatile("cp.async.cg.shared.global [%0], [%1], 16;" \
                 :: "r"(dst), "l"(src) : "memory")
#define CP_COMMIT() asm volatile("cp.async.commit_group;" ::: "memory")
#define CP_WAIT0()  asm volatile("cp.async.wait_group 0;" ::: "memory")

// u32 offset within a 64-u32 row for k-pair kp, permuted order [0,4,1,5,2,6,3,7]
__device__ __forceinline__ int pslot(int kp) {
    int j = kp & 7;
    int s = (j < 4) ? (2 * j) : (2 * (j - 4) + 1);
    return 16 * (kp >> 3) + 2 * s;
}

// m16n8k16 bf16 mma: D += A*B, fp32 accumulate.
__device__ __forceinline__ void mma_bf16(float d[4], const uint32_t a[4],
                                         uint32_t b0, uint32_t b1)
{
    asm volatile(
        "mma.sync.aligned.m16n8k16.row.col.f32.bf16.bf16.f32 "
        "{%0,%1,%2,%3}, {%4,%5,%6,%7}, {%8,%9}, {%0,%1,%2,%3};"
        : "+f"(d[0]), "+f"(d[1]), "+f"(d[2]), "+f"(d[3])
        : "r"(a[0]), "r"(a[1]), "r"(a[2]), "r"(a[3]), "r"(b0), "r"(b1));
}

__device__ __forceinline__ void split2(float x0, float x1,
                                       uint32_t& h, uint32_t& l)
{
    uint32_t hp;
    asm("cvt.rn.bf16x2.f32 %0, %1, %2;" : "=r"(hp) : "f"(x1), "f"(x0));
    float h0 = __uint_as_float(hp << 16);
    float h1 = __uint_as_float(hp & 0xffff0000u);
    uint32_t lp;
    asm("cvt.rn.bf16x2.f32 %0, %1, %2;" : "=r"(lp) : "f"(x1 - h1), "f"(x0 - h0));
    h = hp;
    l = lp;
}

__device__ __forceinline__ void mma3(float d[4],
                                     const uint32_t ah[4], const uint32_t al[4],
                                     uint32_t bh0, uint32_t bl0,
                                     uint32_t bh1, uint32_t bl1)
{
    mma_bf16(d, ah, bh0, bh1);
    mma_bf16(d, ah, bl0, bl1);
    mma_bf16(d, al, bh0, bh1);
}

// ---------------------------------------------------------------------------
// One-shot W pre-split (natural order — proj consumes it as before)
// ---------------------------------------------------------------------------
__global__ __launch_bounds__(256) void wsplit_kernel(
    const float* __restrict__ Wq, const float* __restrict__ Wk,
    const float* __restrict__ Wv)
{
    const int idx = blockIdx.x * 256 + threadIdx.x;
    const int nl = idx & 63;
    const int kp = (idx >> 6) & 511;
    const int m  = idx >> 15;
    const float* Wm = (m == 0) ? Wq : (m == 1 ? Wk : Wv);
    float x0 = Wm[(size_t)(2 * kp) * Hn + nl];
    float x1 = Wm[(size_t)(2 * kp + 1) * Hn + nl];
    uint32_t h, l;
    split2(x0, x1, h, l);
    const int n = m * 64 + nl;
    g_wi[n * 1024 + 2 * kp]     = h;
    g_wi[n * 1024 + 2 * kp + 1] = l;
}

// ---------------------------------------------------------------------------
// Projection: writes q/k pre-split+permuted; V split+transposed in-kernel.
// Warp tiling 2 (M) x 4 (N).
// ---------------------------------------------------------------------------
#define SXI 40
#define SWI 40
#define PJ_X(b) ((b) * 64 * SXI)
#define PJ_W(b) (2 * 64 * SXI + (b) * 192 * SWI)
#define PJ_B    (2 * 64 * SXI + 2 * 192 * SWI)
#define PJ_TOT  (PJ_B + 192)
#define VTS 65   // V staging stride (floats)

__global__ __launch_bounds__(256, 2) void proj_mma_kernel(
    const float* __restrict__ x,
    const float* __restrict__ bq, const float* __restrict__ bk,
    const float* __restrict__ bv)
{
    extern __shared__ uint32_t smu[];
    float* sB = (float*)(smu + PJ_B);

    const int tid  = threadIdx.x;
    const int warp = tid >> 5;
    const int lane = tid & 31;
    const int g    = lane >> 2;
    const int tg   = lane & 3;
    const int wm   = warp & 1;
    const int wn   = warp >> 1;
    const int row0 = blockIdx.x * 64;

    if (tid < 192) {
        const float* bb = (tid < 64) ? bq : (tid < 128 ? bk : bv);
        sB[tid] = bb[tid & 63];
    }

    const int xr = tid >> 3;
    const int xc = tid & 7;

    float acc[2][6][4];
    #pragma unroll
    for (int m2 = 0; m2 < 2; m2++)
        #pragma unroll
        for (int t = 0; t < 6; t++)
            #pragma unroll
            for (int i = 0; i < 4; i++) acc[m2][t][i] = 0.0f;

    float4 xreg[2];
    uint4  wreg[6];

    auto ldg_chunk = [&](int c) {
        const int k0 = c * 32;
        const int kp0 = c * 16;
        #pragma unroll
        for (int u = 0; u < 2; u++) {
            int r = xr + 32 * u;
            xreg[u] = *reinterpret_cast<const float4*>(
                &x[(size_t)(row0 + r) * En + k0 + 4 * xc]);
        }
        #pragma unroll
        for (int u = 0; u < 6; u++) {
            int unit = tid + 256 * u;
            int q = unit & 7, n = unit >> 3;
            wreg[u] = *reinterpret_cast<const uint4*>(
                &g_wi[n * 1024 + 2 * kp0 + 4 * q]);
        }
    };

    auto sts_chunk = [&](int buf) {
        uint32_t* sX = smu + PJ_X(buf);
        uint32_t* sW = smu + PJ_W(buf);
        #pragma unroll
        for (int u = 0; u < 2; u++) {
            int r = xr + 32 * u;
            uint4 o;
            split2(xreg[u].x, xreg[u].y, o.x, o.y);
            split2(xreg[u].z, xreg[u].w, o.z, o.w);
            *reinterpret_cast<uint4*>(&sX[r * SXI + 4 * xc]) = o;
        }
        #pragma unroll
        for (int u = 0; u < 6; u++) {
            int unit = tid + 256 * u;
            int q = unit & 7, n = unit >> 3;
            *reinterpret_cast<uint4*>(&sW[n * SWI + 4 * q]) = wreg[u];
        }
    };

    ldg_chunk(0);
    sts_chunk(0);
    __syncthreads();

    const int NCH = En / 32;
    for (int c = 0; c < NCH; c++) {
        const int buf = c & 1;
        if (c + 1 < NCH) ldg_chunk(c + 1);

        const uint32_t* sX = smu + PJ_X(buf);
        const uint32_t* sW = smu + PJ_W(buf);

        #pragma unroll
        for (int kk = 0; kk < 2; kk++) {
            uint32_t ah[2][4], al[2][4];
            #pragma unroll
            for (int m2 = 0; m2 < 2; m2++) {
                const int a0 = (32 * wm + 16 * m2 + g) * SXI + 2 * (8 * kk + tg);
                uint2 u01 = *reinterpret_cast<const uint2*>(&sX[a0]);
                uint2 u23 = *reinterpret_cast<const uint2*>(&sX[a0 + 8]);
                uint2 u45 = *reinterpret_cast<const uint2*>(&sX[a0 + 8 * SXI]);
                uint2 u67 = *reinterpret_cast<const uint2*>(&sX[a0 + 8 * SXI + 8]);
                ah[m2][0] = u01.x; al[m2][0] = u01.y;
                ah[m2][2] = u23.x; al[m2][2] = u23.y;
                ah[m2][1] = u45.x; al[m2][1] = u45.y;
                ah[m2][3] = u67.x; al[m2][3] = u67.y;
            }
            #pragma unroll
            for (int t = 0; t < 6; t++) {
                const int n = wn * 48 + 8 * t + g;
                const int b0 = n * SWI + 2 * (8 * kk + tg);
                uint2 bh = *reinterpret_cast<const uint2*>(&sW[b0]);
                uint2 bl = *reinterpret_cast<const uint2*>(&sW[b0 + 8]);
                mma3(acc[0][t], ah[0], al[0], bh.x, bh.y, bl.x, bl.y);
                mma3(acc[1][t], ah[1], al[1], bh.x, bh.y, bl.x, bl.y);
            }
        }

        if (c + 1 < NCH) sts_chunk(buf ^ 1);
        __syncthreads();
    }

    // Epilogue: q/k -> gmem (permuted pairs); V -> smem staging (fp32)
    float* sVt = (float*)smu;    // 64 kv-rows x 65 h (reuses freed X buffers)
    #pragma unroll
    for (int m2 = 0; m2 < 2; m2++) {
        const int rl = 32 * wm + 16 * m2 + g;   // local row 0..63
        const int r0 = row0 + rl;
        #pragma unroll
        for (int t = 0; t < 6; t++) {
            const int col = wn * 48 + 8 * t + 2 * tg;   // even
            float a0 = acc[m2][t][0] + sB[col];
            float a1 = acc[m2][t][1] + sB[col + 1];
            float a2 = acc[m2][t][2] + sB[col];
            float a3 = acc[m2][t][3] + sB[col + 1];
            if (col < 64) {
                const int off = pslot(col >> 1);
                uint2 o;
                split2(a0 * 0.125f, a1 * 0.125f, o.x, o.y);
                *reinterpret_cast<uint2*>(&g_qi[(size_t)r0 * 64 + off]) = o;
                split2(a2 * 0.125f, a3 * 0.125f, o.x, o.y);
                *reinterpret_cast<uint2*>(&g_qi[(size_t)(r0 + 8) * 64 + off]) = o;
            } else if (col < 128) {
                const int off = pslot((col - 64) >> 1);
                uint2 o;
                split2(a0, a1, o.x, o.y);
                *reinterpret_cast<uint2*>(&g_ki[(size_t)r0 * 64 + off]) = o;
                split2(a2, a3, o.x, o.y);
                *reinterpret_cast<uint2*>(&g_ki[(size_t)(r0 + 8) * 64 + off]) = o;
            } else {
                const int h = col - 128;
                sVt[rl * VTS + h]       = a0;
                sVt[rl * VTS + h + 1]   = a1;
                sVt[(rl + 8) * VTS + h]     = a2;
                sVt[(rl + 8) * VTS + h + 1] = a3;
            }
        }
    }
    __syncthreads();

    // Fused vsplit: g_vi[b][h][slot(kp)] = split2(V[2Pl][h], V[2Pl+1][h])
    const int bb  = row0 >> 11;
    const int kb2 = (row0 & 2047) >> 1;   // global kpair base (mult of 32)
    #pragma unroll
    for (int u = 0; u < 8; u++) {
        int idx = tid + 256 * u;          // < 2048
        int h  = idx >> 5;
        int Pl = idx & 31;
        uint2 o;
        split2(sVt[(2 * Pl) * VTS + h], sVt[(2 * Pl + 1) * VTS + h], o.x, o.y);
        const int kp = kb2 + Pl;
        *reinterpret_cast<uint2*>(
            &g_vi[(size_t)(bb * 64 + h) * 2048 + pslot(kp)]) = o;   // FIXED
    }
}

// ---------------------------------------------------------------------------
// Flash attention: BM=64 (4 warps), 4-way split-KV, 3xBF16, cp.async
// double-buffer, register-P, uint4 B-fragments (pair-permuted layout),
// per-row +8*(r&1) smem offset for conflict-free LDS.128, deferred l-reduce.
// ---------------------------------------------------------------------------
#define SKI 72
#define BUFK(b) ((b) * 64 * SKI)
#define BUFV(b) (2 * 64 * SKI + (b) * 64 * SKI)
#define BUFM(b) (4 * 64 * SKI + (b) * 64)
#define AT_TOT  (4 * 64 * SKI + 128)

__global__ __launch_bounds__(128, 3) void attn_mma_kernel(
    const int* __restrict__ mask)
{
    extern __shared__ uint32_t smu[];
    const uint32_t sbase = smem_u32(smu);

    const int b    = blockIdx.y;
    const int qt   = (gridDim.x - 1) - blockIdx.x;
    const int z    = blockIdx.z;
    const int qbase = qt * 64;
    const int tid  = threadIdx.x;
    const int warp = tid >> 5;
    const int lane = tid & 31;
    const int g    = lane >> 2;
    const int tg   = lane & 3;
    const int wrow = warp * 16;
    const int goff = 8 * (g & 1);

    const int nt  = qt + 1;
    const int jt_begin = (nt * z) / NSPLIT;
    const int jt_end   = (nt * (z + 1)) / NSPLIT;

    const uint32_t* qip = g_qi + ((size_t)b * Sn + qbase + wrow) * 64;
    const uint32_t* kip = g_ki + (size_t)b * Sn * 64;
    const uint32_t* vip = g_vi + (size_t)b * 64 * 2048;

    auto prefetch = [&](int jt2, int buf) {
        const int kbase = jt2 * 64;
        #pragma unroll
        for (int u = 0; u < 8; u++) {
            int idx = tid + 128 * u;
            int r = idx >> 4, q4 = idx & 15;
            CP16(sbase + 4 * (BUFK(buf) + r * SKI + 8 * (r & 1) + 4 * q4),
                 kip + (size_t)(kbase + r) * 64 + 4 * q4);
        }
        #pragma unroll
        for (int u = 0; u < 8; u++) {
            int idx = tid + 128 * u;
            int h = idx >> 4, q4 = idx & 15;
            CP16(sbase + 4 * (BUFV(buf) + h * SKI + 8 * (h & 1) + 4 * q4),
                 vip + (size_t)h * 2048 + kbase + 4 * q4);
        }
        if (tid < 16) {
            CP16(sbase + 4 * (BUFM(buf) + 4 * tid),
                 mask + b * Sn + kbase + 4 * tid);
        }
        CP_COMMIT();
    };

    // Q fragments: permuted layout -> 2 uint4 per kc
    uint32_t qh[4][4], ql[4][4];
    #pragma unroll
    for (int kc = 0; kc < 4; kc++) {
        uint4 a = *reinterpret_cast<const uint4*>(
            &qip[(size_t)g * 64 + 16 * kc + 4 * tg]);
        uint4 c = *reinterpret_cast<const uint4*>(
            &qip[(size_t)(g + 8) * 64 + 16 * kc + 4 * tg]);
        qh[kc][0] = a.x; ql[kc][0] = a.y;
        qh[kc][2] = a.z; ql[kc][2] = a.w;
        qh[kc][1] = c.x; ql[kc][1] = c.y;
        qh[kc][3] = c.z; ql[kc][3] = c.w;
    }

    float m0 = -1e30f, m1 = -1e30f, l0 = 0.0f, l1 = 0.0f;  // l per-lane partial
    float o[8][4];
    #pragma unroll
    for (int t = 0; t < 8; t++)
        #pragma unroll
        for (int i = 0; i < 4; i++) o[t][i] = 0.0f;

    if (jt_begin < jt_end)
        prefetch(jt_begin, jt_begin & 1);

    for (int jt = jt_begin; jt < jt_end; jt++) {
        const int buf = jt & 1;
        CP_WAIT0();
        __syncthreads();
        if (jt + 1 < jt_end)
            prefetch(jt + 1, buf ^ 1);

        const int kbase = jt * 64;
        const int coff = kbase - qbase;

        uint32_t* sK = smu + BUFK(buf);
        uint32_t* sV = smu + BUFV(buf);
        const int* sMi = (const int*)(smu + BUFM(buf));

        // S = Q * K^T (uint4 B fragments)
        float s[8][4];
        #pragma unroll
        for (int t = 0; t < 8; t++)
            #pragma unroll
            for (int i = 0; i < 4; i++) s[t][i] = 0.0f;

        #pragma unroll
        for (int t = 0; t < 8; t++) {
            const int krow = (8 * t + g) * SKI + goff;
            #pragma unroll
            for (int kc = 0; kc < 4; kc++) {
                uint4 bb = *reinterpret_cast<const uint4*>(
                    &sK[krow + 16 * kc + 4 * tg]);
                mma3(s[t], qh[kc], ql[kc], bb.x, bb.y, bb.z, bb.w);
            }
        }

        // Mask + online softmax (registers only; l deferred)
        const bool needmask = (coff + 63 > wrow);
        const int r0l = wrow + g;
        float rmax0 = -1e30f, rmax1 = -1e30f;
        #pragma unroll
        for (int t = 0; t < 8; t++) {
            const int c = 8 * t + 2 * tg;
            const float pa0 = sMi[c]     ? 0.0f : -1e30f;
            const float pa1 = sMi[c + 1] ? 0.0f : -1e30f;
            s[t][0] += pa0; s[t][1] += pa1;
            s[t][2] += pa0; s[t][3] += pa1;
            if (needmask) {
                if (coff + c > r0l)         s[t][0] = -1e30f;
                if (coff + c + 1 > r0l)     s[t][1] = -1e30f;
                if (coff + c > r0l + 8)     s[t][2] = -1e30f;
                if (coff + c + 1 > r0l + 8) s[t][3] = -1e30f;
            }
            rmax0 = fmaxf(rmax0, fmaxf(s[t][0], s[t][1]));
            rmax1 = fmaxf(rmax1, fmaxf(s[t][2], s[t][3]));
        }
        rmax0 = fmaxf(rmax0, __shfl_xor_sync(0xffffffffu, rmax0, 1));
        rmax0 = fmaxf(rmax0, __shfl_xor_sync(0xffffffffu, rmax0, 2));
        rmax1 = fmaxf(rmax1, __shfl_xor_sync(0xffffffffu, rmax1, 1));
        rmax1 = fmaxf(rmax1, __shfl_xor_sync(0xffffffffu, rmax1, 2));

        const float mn0 = fmaxf(m0, rmax0);
        const float mn1 = fmaxf(m1, rmax1);
        const float al0 = __expf(m0 - mn0);
        const float al1 = __expf(m1 - mn1);

        float ps0 = 0.0f, ps1 = 0.0f;
        #pragma unroll
        for (int t = 0; t < 8; t++) {
            s[t][0] = __expf(s[t][0] - mn0);
            s[t][1] = __expf(s[t][1] - mn0);
            s[t][2] = __expf(s[t][2] - mn1);
            s[t][3] = __expf(s[t][3] - mn1);
            ps0 += s[t][0] + s[t][1];
            ps1 += s[t][2] + s[t][3];
        }
        l0 = l0 * al0 + ps0;        // per-lane partial; reduced after loop
        l1 = l1 * al1 + ps1;
        m0 = mn0;
        m1 = mn1;
        #pragma unroll
        for (int t = 0; t < 8; t++) {
            o[t][0] *= al0; o[t][1] *= al0;
            o[t][2] *= al1; o[t][3] *= al1;
        }

        // O += P * V — A from own s registers, B as uint4
        #pragma unroll
        for (int kc = 0; kc < 4; kc++) {
            uint32_t ah[4], al_[4];
            split2(s[2 * kc][0],     s[2 * kc][1],     ah[0], al_[0]);
            split2(s[2 * kc][2],     s[2 * kc][3],     ah[1], al_[1]);
            split2(s[2 * kc + 1][0], s[2 * kc + 1][1], ah[2], al_[2]);
            split2(s[2 * kc + 1][2], s[2 * kc + 1][3], ah[3], al_[3]);
            #pragma unroll
            for (int t = 0; t < 8; t++) {
                uint4 bb = *reinterpret_cast<const uint4*>(
                    &sV[(8 * t + g) * SKI + goff + 16 * kc + 4 * tg]);
                mma3(o[t], ah, al_, bb.x, bb.y, bb.z, bb.w);
            }
        }
    }

    // Final l reduction across the 4 lanes of each row group
    l0 += __shfl_xor_sync(0xffffffffu, l0, 1);
    l0 += __shfl_xor_sync(0xffffffffu, l0, 2);
    l1 += __shfl_xor_sync(0xffffffffu, l1, 1);
    l1 += __shfl_xor_sync(0xffffffffu, l1, 2);

    float* op = g_op + (size_t)z * Bn * Sn * Hn;
    float* ml = g_ml + (size_t)z * Bn * Sn * 2;
    const size_t row0 = (size_t)b * Sn + qbase + wrow + g;
    #pragma unroll
    for (int t = 0; t < 8; t++) {
        const int col = 8 * t + 2 * tg;
        float2 w0, w1;
        w0.x = o[t][0]; w0.y = o[t][1];
        w1.x = o[t][2]; w1.y = o[t][3];
        *reinterpret_cast<float2*>(&op[row0 * Hn + col]) = w0;
        *reinterpret_cast<float2*>(&op[(row0 + 8) * Hn + col]) = w1;
    }
    if (tg == 0) {
        ml[row0 * 2]           = m0;
        ml[row0 * 2 + 1]       = l0;
        ml[(row0 + 8) * 2]     = m1;
        ml[(row0 + 8) * 2 + 1] = l1;
    }
}

// ---------------------------------------------------------------------------
// Merge the 4 KV splits
// ---------------------------------------------------------------------------
__global__ __launch_bounds__(256) void merge_kernel(float* __restrict__ out)
{
    const int tid = threadIdx.x;
    const int row = blockIdx.x * 16 + (tid >> 4);
    const int c4  = (tid & 15) * 4;

    float mz[NSPLIT], lz[NSPLIT];
    float m = -1e30f;
    #pragma unroll
    for (int zz = 0; zz < NSPLIT; zz++) {
        mz[zz] = g_ml[(size_t)zz * Bn * Sn * 2 + row * 2];
        lz[zz] = g_ml[(size_t)zz * Bn * Sn * 2 + row * 2 + 1];
        m = fmaxf(m, mz[zz]);
    }
    float denom = 0.0f;
    float w[NSPLIT];
    #pragma unroll
    for (int zz = 0; zz < NSPLIT; zz++) {
        w[zz] = __expf(mz[zz] - m);
        denom += w[zz] * lz[zz];
    }
    const float inv = 1.0f / denom;

    float4 r;
    r.x = 0.0f; r.y = 0.0f; r.z = 0.0f; r.w = 0.0f;
    #pragma unroll
    for (int zz = 0; zz < NSPLIT; zz++) {
        float4 a = *reinterpret_cast<const float4*>(
            &g_op[(size_t)zz * Bn * Sn * Hn + (size_t)row * Hn + c4]);
        r.x += w[zz] * a.x;
        r.y += w[zz] * a.y;
        r.z += w[zz] * a.z;
        r.w += w[zz] * a.w;
    }
    r.x *= inv; r.y *= inv; r.z *= inv; r.w *= inv;
    *reinterpret_cast<float4*>(&out[(size_t)row * Hn + c4]) = r;
}

extern "C" void kernel_launch(void* const* d_in, const int* in_sizes, int n_in,
                              void* d_out, int out_size)
{
    const float* x    = (const float*)d_in[0];
    const int*   mask = (const int*)d_in[1];
    const float* Wq   = (const float*)d_in[2];
    const float* bq   = (const float*)d_in[3];
    const float* Wk   = (const float*)d_in[4];
    const float* bk   = (const float*)d_in[5];
    const float* Wv   = (const float*)d_in[6];
    const float* bv   = (const float*)d_in[7];
    float* out = (float*)d_out;

    cudaFuncSetAttribute(proj_mma_kernel,
                         cudaFuncAttributeMaxDynamicSharedMemorySize,
                         PJ_TOT * (int)sizeof(uint32_t));
    cudaFuncSetAttribute(attn_mma_kernel,
                         cudaFuncAttributeMaxDynamicSharedMemorySize,
                         AT_TOT * (int)sizeof(uint32_t));

    wsplit_kernel<<<384, 256>>>(Wq, Wk, Wv);

    proj_mma_kernel<<<Bn * Sn / 64, 256, PJ_TOT * sizeof(uint32_t)>>>(
        x, bq, bk, bv);

    dim3 gattn(Sn / 64, Bn, NSPLIT);
    attn_mma_kernel<<<gattn, 128, AT_TOT * sizeof(uint32_t)>>>(mask);

    merge_kernel<<<Bn * Sn / 16, 256>>>(out);
}

// round 17
// speedup vs baseline: 1.0956x; 1.0956x over previous
#include <cuda_runtime.h>
#include <math.h>
#include <cstdint>

#define Bn 8
#define Sn 2048
#define En 1024
#define Hn 64
#define NSPLIT 4

// Scratch: v [B,S,H] fp32; q,k,v pre-split bf16-pair forms; partials; W split
__device__ float g_v[Bn * Sn * Hn];
__device__ uint32_t g_qi[Bn * Sn * 64];   // q: (h,l) pairs along h, PRE-SCALED
__device__ uint32_t g_ki[Bn * Sn * 64];   // k: (h,l) pairs along h
__device__ uint32_t g_vi[Bn * 64 * 2048]; // v: [b][h][kvpair] (h,l) pairs along kv
__device__ float g_op[NSPLIT * Bn * Sn * Hn];
__device__ float g_ml[NSPLIT * Bn * Sn * 2];
__device__ uint32_t g_wi[192 * 1024];     // W: (h,l) pairs along k

__device__ __forceinline__ uint32_t smem_u32(const void* p) {
    uint32_t a;
    asm("{ .reg .u64 t; cvta.to.shared.u64 t, %1; cvt.u32.u64 %0, t; }"
        : "=r"(a) : "l"(p));
    return a;
}

#define CP16(dst, src) \
    asm volatile("cp.async.cg.shared.global [%0], [%1], 16;" \
                 :: "r"(dst), "l"(src) : "memory")
#define CP_COMMIT() asm volatile("cp.async.commit_group;" ::: "memory")
#define CP_WAIT0()  asm volatile("cp.async.wait_group 0;" ::: "memory")

// m16n8k16 bf16 mma: D += A*B, fp32 accumulate.
__device__ __forceinline__ void mma_bf16(float d[4], const uint32_t a[4],
                                         uint32_t b0, uint32_t b1)
{
    asm volatile(
        "mma.sync.aligned.m16n8k16.row.col.f32.bf16.bf16.f32 "
        "{%0,%1,%2,%3}, {%4,%5,%6,%7}, {%8,%9}, {%0,%1,%2,%3};"
        : "+f"(d[0]), "+f"(d[1]), "+f"(d[2]), "+f"(d[3])
        : "r"(a[0]), "r"(a[1]), "r"(a[2]), "r"(a[3]), "r"(b0), "r"(b1));
}

__device__ __forceinline__ void split2(float x0, float x1,
                                       uint32_t& h, uint32_t& l)
{
    uint32_t hp;
    asm("cvt.rn.bf16x2.f32 %0, %1, %2;" : "=r"(hp) : "f"(x1), "f"(x0));
    float h0 = __uint_as_float(hp << 16);
    float h1 = __uint_as_float(hp & 0xffff0000u);
    uint32_t lp;
    asm("cvt.rn.bf16x2.f32 %0, %1, %2;" : "=r"(lp) : "f"(x1 - h1), "f"(x0 - h0));
    h = hp;
    l = lp;
}

__device__ __forceinline__ void mma3(float d[4],
                                     const uint32_t ah[4], const uint32_t al[4],
                                     uint32_t bh0, uint32_t bl0,
                                     uint32_t bh1, uint32_t bl1)
{
    mma_bf16(d, ah, bh0, bh1);
    mma_bf16(d, ah, bl0, bl1);
    mma_bf16(d, al, bh0, bh1);
}

// ---------------------------------------------------------------------------
// One-shot W pre-split
// ---------------------------------------------------------------------------
__global__ __launch_bounds__(256) void wsplit_kernel(
    const float* __restrict__ Wq, const float* __restrict__ Wk,
    const float* __restrict__ Wv)
{
    const int idx = blockIdx.x * 256 + threadIdx.x;
    const int nl = idx & 63;
    const int kp = (idx >> 6) & 511;
    const int m  = idx >> 15;
    const float* Wm = (m == 0) ? Wq : (m == 1 ? Wk : Wv);
    float x0 = Wm[(size_t)(2 * kp) * Hn + nl];
    float x1 = Wm[(size_t)(2 * kp + 1) * Hn + nl];
    uint32_t h, l;
    split2(x0, x1, h, l);
    const int n = m * 64 + nl;
    g_wi[n * 1024 + 2 * kp]     = h;
    g_wi[n * 1024 + 2 * kp + 1] = l;
}

// ---------------------------------------------------------------------------
// One-shot V pre-split+transpose
// ---------------------------------------------------------------------------
__global__ __launch_bounds__(256) void vsplit_kernel()
{
    __shared__ float t[64][65];
    const int b  = blockIdx.y;
    const int kbase = blockIdx.x * 64;
    const int tid = threadIdx.x;

    #pragma unroll
    for (int u = 0; u < 16; u++) {
        int idx = tid + 256 * u;
        int kv = idx >> 6, h = idx & 63;
        t[kv][h] = g_v[((size_t)b * Sn + kbase + kv) * Hn + h];
    }
    __syncthreads();
    #pragma unroll
    for (int u = 0; u < 8; u++) {
        int idx = tid + 256 * u;
        int h = idx >> 5, Pl = idx & 31;
        uint32_t hh, ll;
        split2(t[2 * Pl][h], t[2 * Pl + 1][h], hh, ll);
        uint2 o; o.x = hh; o.y = ll;
        *reinterpret_cast<uint2*>(
            &g_vi[((size_t)(b * 64 + h)) * 2048 + kbase + 2 * Pl]) = o;
    }
}

// ---------------------------------------------------------------------------
// Projection: warp tiling 2 (M, 32 rows) x 4 (N, 48 cols)
// ---------------------------------------------------------------------------
#define SXI 40
#define SWI 40
#define PJ_X(b) ((b) * 64 * SXI)
#define PJ_W(b) (2 * 64 * SXI + (b) * 192 * SWI)
#define PJ_B    (2 * 64 * SXI + 2 * 192 * SWI)
#define PJ_TOT  (PJ_B + 192)

__global__ __launch_bounds__(256, 2) void proj_mma_kernel(
    const float* __restrict__ x,
    const float* __restrict__ bq, const float* __restrict__ bk,
    const float* __restrict__ bv)
{
    extern __shared__ uint32_t smu[];
    float* sB = (float*)(smu + PJ_B);

    const int tid  = threadIdx.x;
    const int warp = tid >> 5;
    const int lane = tid & 31;
    const int g    = lane >> 2;
    const int tg   = lane & 3;
    const int wm   = warp & 1;
    const int wn   = warp >> 1;
    const int row0 = blockIdx.x * 64;

    if (tid < 192) {
        const float* bb = (tid < 64) ? bq : (tid < 128 ? bk : bv);
        sB[tid] = bb[tid & 63];
    }

    const int xr = tid >> 3;
    const int xc = tid & 7;

    float acc[2][6][4];
    #pragma unroll
    for (int m2 = 0; m2 < 2; m2++)
        #pragma unroll
        for (int t = 0; t < 6; t++)
            #pragma unroll
            for (int i = 0; i < 4; i++) acc[m2][t][i] = 0.0f;

    float4 xreg[2];
    uint4  wreg[6];

    auto ldg_chunk = [&](int c) {
        const int k0 = c * 32;
        const int kp0 = c * 16;
        #pragma unroll
        for (int u = 0; u < 2; u++) {
            int r = xr + 32 * u;
            xreg[u] = *reinterpret_cast<const float4*>(
                &x[(size_t)(row0 + r) * En + k0 + 4 * xc]);
        }
        #pragma unroll
        for (int u = 0; u < 6; u++) {
            int unit = tid + 256 * u;
            int q = unit & 7, n = unit >> 3;
            wreg[u] = *reinterpret_cast<const uint4*>(
                &g_wi[n * 1024 + 2 * kp0 + 4 * q]);
        }
    };

    auto sts_chunk = [&](int buf) {
        uint32_t* sX = smu + PJ_X(buf);
        uint32_t* sW = smu + PJ_W(buf);
        #pragma unroll
        for (int u = 0; u < 2; u++) {
            int r = xr + 32 * u;
            uint4 o;
            split2(xreg[u].x, xreg[u].y, o.x, o.y);
            split2(xreg[u].z, xreg[u].w, o.z, o.w);
            *reinterpret_cast<uint4*>(&sX[r * SXI + 4 * xc]) = o;
        }
        #pragma unroll
        for (int u = 0; u < 6; u++) {
            int unit = tid + 256 * u;
            int q = unit & 7, n = unit >> 3;
            *reinterpret_cast<uint4*>(&sW[n * SWI + 4 * q]) = wreg[u];
        }
    };

    ldg_chunk(0);
    sts_chunk(0);
    __syncthreads();

    const int NCH = En / 32;
    for (int c = 0; c < NCH; c++) {
        const int buf = c & 1;
        if (c + 1 < NCH) ldg_chunk(c + 1);

        const uint32_t* sX = smu + PJ_X(buf);
        const uint32_t* sW = smu + PJ_W(buf);

        #pragma unroll
        for (int kk = 0; kk < 2; kk++) {
            uint32_t ah[2][4], al[2][4];
            #pragma unroll
            for (int m2 = 0; m2 < 2; m2++) {
                const int a0 = (32 * wm + 16 * m2 + g) * SXI + 2 * (8 * kk + tg);
                uint2 u01 = *reinterpret_cast<const uint2*>(&sX[a0]);
                uint2 u23 = *reinterpret_cast<const uint2*>(&sX[a0 + 8]);
                uint2 u45 = *reinterpret_cast<const uint2*>(&sX[a0 + 8 * SXI]);
                uint2 u67 = *reinterpret_cast<const uint2*>(&sX[a0 + 8 * SXI + 8]);
                ah[m2][0] = u01.x; al[m2][0] = u01.y;
                ah[m2][2] = u23.x; al[m2][2] = u23.y;
                ah[m2][1] = u45.x; al[m2][1] = u45.y;
                ah[m2][3] = u67.x; al[m2][3] = u67.y;
            }
            #pragma unroll
            for (int t = 0; t < 6; t++) {
                const int n = wn * 48 + 8 * t + g;
                const int b0 = n * SWI + 2 * (8 * kk + tg);
                uint2 bh = *reinterpret_cast<const uint2*>(&sW[b0]);
                uint2 bl = *reinterpret_cast<const uint2*>(&sW[b0 + 8]);
                mma3(acc[0][t], ah[0], al[0], bh.x, bh.y, bl.x, bl.y);
                mma3(acc[1][t], ah[1], al[1], bh.x, bh.y, bl.x, bl.y);
            }
        }

        if (c + 1 < NCH) sts_chunk(buf ^ 1);
        __syncthreads();
    }

    #pragma unroll
    for (int m2 = 0; m2 < 2; m2++) {
        const int r0 = row0 + 32 * wm + 16 * m2 + g;
        #pragma unroll
        for (int t = 0; t < 6; t++) {
            const int col = wn * 48 + 8 * t + 2 * tg;   // even
            float a0 = acc[m2][t][0] + sB[col];
            float a1 = acc[m2][t][1] + sB[col + 1];
            float a2 = acc[m2][t][2] + sB[col];
            float a3 = acc[m2][t][3] + sB[col + 1];
            if (col < 64) {
                uint2 o;
                split2(a0 * 0.125f, a1 * 0.125f, o.x, o.y);
                *reinterpret_cast<uint2*>(&g_qi[(size_t)r0 * 64 + col]) = o;
                split2(a2 * 0.125f, a3 * 0.125f, o.x, o.y);
                *reinterpret_cast<uint2*>(&g_qi[(size_t)(r0 + 8) * 64 + col]) = o;
            } else if (col < 128) {
                uint2 o;
                split2(a0, a1, o.x, o.y);
                *reinterpret_cast<uint2*>(&g_ki[(size_t)r0 * 64 + col - 64]) = o;
                split2(a2, a3, o.x, o.y);
                *reinterpret_cast<uint2*>(&g_ki[(size_t)(r0 + 8) * 64 + col - 64]) = o;
            } else {
                const int lcol = col - 128;
                float2 v0, v1;
                v0.x = a0; v0.y = a1;
                v1.x = a2; v1.y = a3;
                *reinterpret_cast<float2*>(&g_v[(size_t)r0 * Hn + lcol]) = v0;
                *reinterpret_cast<float2*>(&g_v[(size_t)(r0 + 8) * Hn + lcol]) = v1;
            }
        }
    }
}

// ---------------------------------------------------------------------------
// Flash attention: BM=64 (4 warps, 128 thr), 4-way split-KV, 3xBF16,
// cp.async double-buffered K/V/mask, register-P, DEFERRED l-reduction.
// ---------------------------------------------------------------------------
#define SKI 72
#define SVI 72
#define BUFK(b) ((b) * 64 * SKI)
#define BUFV(b) (2 * 64 * SKI + (b) * 64 * SVI)
#define BUFM(b) (2 * 64 * SKI + 2 * 64 * SVI + (b) * 64)
#define AT_TOT  (2 * 64 * SKI + 2 * 64 * SVI + 128)

__global__ __launch_bounds__(128, 3) void attn_mma_kernel(
    const int* __restrict__ mask)
{
    extern __shared__ uint32_t smu[];
    const uint32_t sbase = smem_u32(smu);

    const int b    = blockIdx.y;
    const int qt   = (gridDim.x - 1) - blockIdx.x;   // heavy q-tiles first
    const int z    = blockIdx.z;
    const int qbase = qt * 64;
    const int tid  = threadIdx.x;
    const int warp = tid >> 5;          // 0..3
    const int lane = tid & 31;
    const int g    = lane >> 2;
    const int tg   = lane & 3;
    const int wrow = warp * 16;

    const int nt  = qt + 1;
    const int jt_begin = (nt * z) / NSPLIT;
    const int jt_end   = (nt * (z + 1)) / NSPLIT;

    const uint32_t* qip = g_qi + ((size_t)b * Sn + qbase + wrow) * 64;
    const uint32_t* kip = g_ki + (size_t)b * Sn * 64;
    const uint32_t* vip = g_vi + (size_t)b * 64 * 2048;

    auto prefetch = [&](int jt2, int buf) {
        const int kbase = jt2 * 64;
        #pragma unroll
        for (int u = 0; u < 8; u++) {
            int idx = tid + 128 * u;
            int r = idx >> 4, q4 = idx & 15;
            CP16(sbase + 4 * (BUFK(buf) + r * SKI + 4 * q4),
                 kip + (size_t)(kbase + r) * 64 + 4 * q4);
        }
        #pragma unroll
        for (int u = 0; u < 8; u++) {
            int idx = tid + 128 * u;
            int h = idx >> 4, q4 = idx & 15;
            CP16(sbase + 4 * (BUFV(buf) + h * SVI + 4 * q4),
                 vip + (size_t)h * 2048 + kbase + 4 * q4);
        }
        if (tid < 16) {
            CP16(sbase + 4 * (BUFM(buf) + 4 * tid),
                 mask + b * Sn + kbase + 4 * tid);
        }
        CP_COMMIT();
    };

    // Q fragments (already scaled + split by proj)
    uint32_t qh[4][4], ql[4][4];
    #pragma unroll
    for (int kc = 0; kc < 4; kc++) {
        const int hp = 8 * kc + tg;
        uint2 a0 = *reinterpret_cast<const uint2*>(&qip[(size_t)g * 64 + 2 * hp]);
        uint2 a1 = *reinterpret_cast<const uint2*>(&qip[(size_t)(g + 8) * 64 + 2 * hp]);
        uint2 a2 = *reinterpret_cast<const uint2*>(&qip[(size_t)g * 64 + 2 * hp + 8]);
        uint2 a3 = *reinterpret_cast<const uint2*>(&qip[(size_t)(g + 8) * 64 + 2 * hp + 8]);
        qh[kc][0] = a0.x; ql[kc][0] = a0.y;
        qh[kc][1] = a1.x; ql[kc][1] = a1.y;
        qh[kc][2] = a2.x; ql[kc][2] = a2.y;
        qh[kc][3] = a3.x; ql[kc][3] = a3.y;
    }

    float m0 = -1e30f, m1 = -1e30f;
    float l0 = 0.0f, l1 = 0.0f;         // per-lane partials, reduced at end
    float o[8][4];
    #pragma unroll
    for (int t = 0; t < 8; t++)
        #pragma unroll
        for (int i = 0; i < 4; i++) o[t][i] = 0.0f;

    if (jt_begin < jt_end)
        prefetch(jt_begin, jt_begin & 1);

    for (int jt = jt_begin; jt < jt_end; jt++) {
        const int buf = jt & 1;
        CP_WAIT0();
        __syncthreads();            // tile resident; prev buffers free
        if (jt + 1 < jt_end)
            prefetch(jt + 1, buf ^ 1);

        const int kbase = jt * 64;
        const int coff = kbase - qbase;

        uint32_t* sK = smu + BUFK(buf);
        uint32_t* sV = smu + BUFV(buf);
        const int* sMi = (const int*)(smu + BUFM(buf));

        // S = Q * K^T
        float s[8][4];
        #pragma unroll
        for (int t = 0; t < 8; t++)
            #pragma unroll
            for (int i = 0; i < 4; i++) s[t][i] = 0.0f;

        #pragma unroll
        for (int t = 0; t < 8; t++) {
            const int krow = (8 * t + g) * SKI;
            #pragma unroll
            for (int kc = 0; kc < 4; kc++) {
                uint2 b0 = *reinterpret_cast<const uint2*>(
                    &sK[krow + 2 * (8 * kc + tg)]);
                uint2 b1 = *reinterpret_cast<const uint2*>(
                    &sK[krow + 2 * (8 * kc + tg) + 8]);
                mma3(s[t], qh[kc], ql[kc], b0.x, b0.y, b1.x, b1.y);
            }
        }

        // Mask + online softmax (registers only; l deferred)
        const bool needmask = (coff + 63 > wrow);
        const int r0l = wrow + g;
        float rmax0 = -1e30f, rmax1 = -1e30f;
        #pragma unroll
        for (int t = 0; t < 8; t++) {
            const int c = 8 * t + 2 * tg;
            const float pa0 = sMi[c]     ? 0.0f : -1e30f;
            const float pa1 = sMi[c + 1] ? 0.0f : -1e30f;
            s[t][0] += pa0; s[t][1] += pa1;
            s[t][2] += pa0; s[t][3] += pa1;
            if (needmask) {
                if (coff + c > r0l)         s[t][0] = -1e30f;
                if (coff + c + 1 > r0l)     s[t][1] = -1e30f;
                if (coff + c > r0l + 8)     s[t][2] = -1e30f;
                if (coff + c + 1 > r0l + 8) s[t][3] = -1e30f;
            }
            rmax0 = fmaxf(rmax0, fmaxf(s[t][0], s[t][1]));
            rmax1 = fmaxf(rmax1, fmaxf(s[t][2], s[t][3]));
        }
        rmax0 = fmaxf(rmax0, __shfl_xor_sync(0xffffffffu, rmax0, 1));
        rmax0 = fmaxf(rmax0, __shfl_xor_sync(0xffffffffu, rmax0, 2));
        rmax1 = fmaxf(rmax1, __shfl_xor_sync(0xffffffffu, rmax1, 1));
        rmax1 = fmaxf(rmax1, __shfl_xor_sync(0xffffffffu, rmax1, 2));

        const float mn0 = fmaxf(m0, rmax0);
        const float mn1 = fmaxf(m1, rmax1);
        const float al0 = __expf(m0 - mn0);
        const float al1 = __expf(m1 - mn1);

        float ps0 = 0.0f, ps1 = 0.0f;
        #pragma unroll
        for (int t = 0; t < 8; t++) {
            s[t][0] = __expf(s[t][0] - mn0);
            s[t][1] = __expf(s[t][1] - mn0);
            s[t][2] = __expf(s[t][2] - mn1);
            s[t][3] = __expf(s[t][3] - mn1);
            ps0 += s[t][0] + s[t][1];
            ps1 += s[t][2] + s[t][3];
        }
        l0 = l0 * al0 + ps0;        // per-lane; alphas are lane-uniform
        l1 = l1 * al1 + ps1;
        m0 = mn0;
        m1 = mn1;
        #pragma unroll
        for (int t = 0; t < 8; t++) {
            o[t][0] *= al0; o[t][1] *= al0;
            o[t][2] *= al1; o[t][3] *= al1;
        }

        // O += P * V — A fragments built from this thread's own s registers
        #pragma unroll
        for (int kc = 0; kc < 4; kc++) {
            uint32_t ah[4], al_[4];
            split2(s[2 * kc][0],     s[2 * kc][1],     ah[0], al_[0]);
            split2(s[2 * kc][2],     s[2 * kc][3],     ah[1], al_[1]);
            split2(s[2 * kc + 1][0], s[2 * kc + 1][1], ah[2], al_[2]);
            split2(s[2 * kc + 1][2], s[2 * kc + 1][3], ah[3], al_[3]);
            #pragma unroll
            for (int t = 0; t < 8; t++) {
                const int vr = (8 * t + g) * SVI + 2 * (8 * kc + tg);
                uint2 b0 = *reinterpret_cast<const uint2*>(&sV[vr]);
                uint2 b1 = *reinterpret_cast<const uint2*>(&sV[vr + 8]);
                mma3(o[t], ah, al_, b0.x, b0.y, b1.x, b1.y);
            }
        }
    }

    // Deferred l reduction across the 4 lanes of each row group
    l0 += __shfl_xor_sync(0xffffffffu, l0, 1);
    l0 += __shfl_xor_sync(0xffffffffu, l0, 2);
    l1 += __shfl_xor_sync(0xffffffffu, l1, 1);
    l1 += __shfl_xor_sync(0xffffffffu, l1, 2);

    float* op = g_op + (size_t)z * Bn * Sn * Hn;
    float* ml = g_ml + (size_t)z * Bn * Sn * 2;
    const size_t row0 = (size_t)b * Sn + qbase + wrow + g;
    #pragma unroll
    for (int t = 0; t < 8; t++) {
        const int col = 8 * t + 2 * tg;
        float2 w0, w1;
        w0.x = o[t][0]; w0.y = o[t][1];
        w1.x = o[t][2]; w1.y = o[t][3];
        *reinterpret_cast<float2*>(&op[row0 * Hn + col]) = w0;
        *reinterpret_cast<float2*>(&op[(row0 + 8) * Hn + col]) = w1;
    }
    if (tg == 0) {
        ml[row0 * 2]           = m0;
        ml[row0 * 2 + 1]       = l0;
        ml[(row0 + 8) * 2]     = m1;
        ml[(row0 + 8) * 2 + 1] = l1;
    }
}

// ---------------------------------------------------------------------------
// Merge the 4 KV splits
// ---------------------------------------------------------------------------
__global__ __launch_bounds__(256) void merge_kernel(float* __restrict__ out)
{
    const int tid = threadIdx.x;
    const int row = blockIdx.x * 16 + (tid >> 4);
    const int c4  = (tid & 15) * 4;

    float mz[NSPLIT], lz[NSPLIT];
    float m = -1e30f;
    #pragma unroll
    for (int zz = 0; zz < NSPLIT; zz++) {
        mz[zz] = g_ml[(size_t)zz * Bn * Sn * 2 + row * 2];
        lz[zz] = g_ml[(size_t)zz * Bn * Sn * 2 + row * 2 + 1];
        m = fmaxf(m, mz[zz]);
    }
    float denom = 0.0f;
    float w[NSPLIT];
    #pragma unroll
    for (int zz = 0; zz < NSPLIT; zz++) {
        w[zz] = __expf(mz[zz] - m);
        denom += w[zz] * lz[zz];
    }
    const float inv = 1.0f / denom;

    float4 r;
    r.x = 0.0f; r.y = 0.0f; r.z = 0.0f; r.w = 0.0f;
    #pragma unroll
    for (int zz = 0; zz < NSPLIT; zz++) {
        float4 a = *reinterpret_cast<const float4*>(
            &g_op[(size_t)zz * Bn * Sn * Hn + (size_t)row * Hn + c4]);
        r.x += w[zz] * a.x;
        r.y += w[zz] * a.y;
        r.z += w[zz] * a.z;
        r.w += w[zz] * a.w;
    }
    r.x *= inv; r.y *= inv; r.z *= inv; r.w *= inv;
    *reinterpret_cast<float4*>(&out[(size_t)row * Hn + c4]) = r;
}

extern "C" void kernel_launch(void* const* d_in, const int* in_sizes, int n_in,
                              void* d_out, int out_size)
{
    const float* x    = (const float*)d_in[0];
    const int*   mask = (const int*)d_in[1];
    const float* Wq   = (const float*)d_in[2];
    const float* bq   = (const float*)d_in[3];
    const float* Wk   = (const float*)d_in[4];
    const float* bk   = (const float*)d_in[5];
    const float* Wv   = (const float*)d_in[6];
    const float* bv   = (const float*)d_in[7];
    float* out = (float*)d_out;

    cudaFuncSetAttribute(proj_mma_kernel,
                         cudaFuncAttributeMaxDynamicSharedMemorySize,
                         PJ_TOT * (int)sizeof(uint32_t));
    cudaFuncSetAttribute(attn_mma_kernel,
                         cudaFuncAttributeMaxDynamicSharedMemorySize,
                         AT_TOT * (int)sizeof(uint32_t));

    wsplit_kernel<<<384, 256>>>(Wq, Wk, Wv);

    proj_mma_kernel<<<Bn * Sn / 64, 256, PJ_TOT * sizeof(uint32_t)>>>(
        x, bq, bk, bv);

    dim3 gvs(Sn / 64, Bn);
    vsplit_kernel<<<gvs, 256>>>();

    dim3 gattn(Sn / 64, Bn, NSPLIT);
    attn_mma_kernel<<<gattn, 128, AT_TOT * sizeof(uint32_t)>>>(mask);

    merge_kernel<<<Bn * Sn / 16, 256>>>(out);
}